// round 8
// baseline (speedup 1.0000x reference)
#include <cuda_runtime.h>
#include <math.h>

// ---------------------------------------------------------------------------
// AV_Attention: B=8, S=2048, INPUT_DIM=1024, DIM_K=DIM_V=1024, fp32.
//   Q = img @ q_w^T + q_b ; K = text @ k_w^T + k_b ; V = text @ v_w^T + v_b
//   scores = Q @ K^T (per batch)  [NO pre-softmax scaling — quirk!]
//   atten  = softmax(scores) * (1/sqrt(1024))
//   output = atten @ V ; feature = output + text
// Outputs flattened: d_out[0:16777216)=output, d_out[16777216:33554432)=feature
// ---------------------------------------------------------------------------

static __device__ float g_Q[16777216];   // 64 MB
static __device__ float g_K[16777216];   // 64 MB
static __device__ float g_V[16777216];   // 64 MB
static __device__ float g_S[33554432];   // 128 MB (scores / atten)

constexpr int BM = 128, BN = 128, BK = 16;

// ---------------------------------------------------------------------------
// Generic 128x128x16 double-buffered SGEMM.
//  C = A @ B^T (TRANSB=true, B is [N,K] row-major)   or
//  C = A @ B   (TRANSB=false, B is [K,N] row-major)
//  BIAS : add bias[col]
//  AVEPI: write C and feat = C + text
// Grid: (N/128, M/128, batches). All dims must divide the tiles (they do).
// ---------------------------------------------------------------------------
template <bool TRANSB, bool BIAS, bool AVEPI>
__global__ void __launch_bounds__(256, 2)
gemm_k(const float* __restrict__ A, const float* __restrict__ B,
       const float* __restrict__ bias, float* __restrict__ C,
       const float* __restrict__ text, float* __restrict__ feat,
       int K, int lda, int ldb, int ldc,
       long long sA, long long sB, long long sC)
{
    __shared__ float As[2][BK][BM + 4];
    __shared__ float Bs[2][BK][BN + 4];

    const int z = blockIdx.z;
    A += (long long)z * sA;
    B += (long long)z * sB;
    C += (long long)z * sC;
    if (AVEPI) { text += (long long)z * sC; feat += (long long)z * sC; }

    const int tid = threadIdx.x;
    const int tx = tid & 15;
    const int ty = tid >> 4;
    const int bx = blockIdx.x, by = blockIdx.y;

    // A loader: 128 rows x 16 k, transpose-store. 2 float4 per thread.
    const int arow = tid >> 2;            // 0..63
    const int acol = (tid & 3) << 2;      // 0,4,8,12
    const float* Aptr0 = A + (long long)(by * BM + arow) * lda + acol;
    const float* Aptr1 = Aptr0 + 64LL * lda;

    // B loader
    const float* Bptr0;
    const float* Bptr1;
    int bk_row = 0, bn_col = 0;
    if (TRANSB) {
        Bptr0 = B + (long long)(bx * BN + arow) * ldb + acol;
        Bptr1 = Bptr0 + 64LL * ldb;
    } else {
        bk_row = tid >> 5;                // 0..7
        bn_col = (tid & 31) << 2;         // 0..124
        Bptr0 = B + (long long)bk_row * ldb + bx * BN + bn_col;
        Bptr1 = Bptr0 + 8LL * ldb;
    }

    auto ld_tile = [&](int k0, float4& va0, float4& va1, float4& vb0, float4& vb1) {
        va0 = *reinterpret_cast<const float4*>(Aptr0 + k0);
        va1 = *reinterpret_cast<const float4*>(Aptr1 + k0);
        if (TRANSB) {
            vb0 = *reinterpret_cast<const float4*>(Bptr0 + k0);
            vb1 = *reinterpret_cast<const float4*>(Bptr1 + k0);
        } else {
            vb0 = *reinterpret_cast<const float4*>(Bptr0 + (long long)k0 * ldb);
            vb1 = *reinterpret_cast<const float4*>(Bptr1 + (long long)k0 * ldb);
        }
    };

    auto st_tile = [&](int s, float4 va0, float4 va1, float4 vb0, float4 vb1) {
        As[s][acol + 0][arow] = va0.x;
        As[s][acol + 1][arow] = va0.y;
        As[s][acol + 2][arow] = va0.z;
        As[s][acol + 3][arow] = va0.w;
        As[s][acol + 0][arow + 64] = va1.x;
        As[s][acol + 1][arow + 64] = va1.y;
        As[s][acol + 2][arow + 64] = va1.z;
        As[s][acol + 3][arow + 64] = va1.w;
        if (TRANSB) {
            Bs[s][acol + 0][arow] = vb0.x;
            Bs[s][acol + 1][arow] = vb0.y;
            Bs[s][acol + 2][arow] = vb0.z;
            Bs[s][acol + 3][arow] = vb0.w;
            Bs[s][acol + 0][arow + 64] = vb1.x;
            Bs[s][acol + 1][arow + 64] = vb1.y;
            Bs[s][acol + 2][arow + 64] = vb1.z;
            Bs[s][acol + 3][arow + 64] = vb1.w;
        } else {
            *reinterpret_cast<float4*>(&Bs[s][bk_row][bn_col]) = vb0;
            *reinterpret_cast<float4*>(&Bs[s][bk_row + 8][bn_col]) = vb1;
        }
    };

    float acc[8][8];
#pragma unroll
    for (int i = 0; i < 8; ++i)
#pragma unroll
        for (int j = 0; j < 8; ++j) acc[i][j] = 0.0f;

    {
        float4 a0, a1, b0, b1;
        ld_tile(0, a0, a1, b0, b1);
        st_tile(0, a0, a1, b0, b1);
    }
    __syncthreads();

    const int nk = K / BK;
    for (int kt = 0; kt < nk; ++kt) {
        const int s = kt & 1;
        float4 na0, na1, nb0, nb1;
        const bool pf = (kt + 1 < nk);
        if (pf) ld_tile((kt + 1) * BK, na0, na1, nb0, nb1);

#pragma unroll
        for (int kk = 0; kk < BK; ++kk) {
            float4 xa0 = *reinterpret_cast<const float4*>(&As[s][kk][ty * 8]);
            float4 xa1 = *reinterpret_cast<const float4*>(&As[s][kk][ty * 8 + 4]);
            float4 xb0 = *reinterpret_cast<const float4*>(&Bs[s][kk][tx * 8]);
            float4 xb1 = *reinterpret_cast<const float4*>(&Bs[s][kk][tx * 8 + 4]);
            float ar[8] = {xa0.x, xa0.y, xa0.z, xa0.w, xa1.x, xa1.y, xa1.z, xa1.w};
            float br[8] = {xb0.x, xb0.y, xb0.z, xb0.w, xb1.x, xb1.y, xb1.z, xb1.w};
#pragma unroll
            for (int i = 0; i < 8; ++i)
#pragma unroll
                for (int j = 0; j < 8; ++j)
                    acc[i][j] = fmaf(ar[i], br[j], acc[i][j]);
        }

        if (pf) st_tile(s ^ 1, na0, na1, nb0, nb1);
        __syncthreads();
    }

    // Epilogue
    const int row0 = by * BM + ty * 8;
    const int col0 = bx * BN + tx * 8;
    float4 bi0, bi1;
    if (BIAS) {
        bi0 = *reinterpret_cast<const float4*>(bias + col0);
        bi1 = *reinterpret_cast<const float4*>(bias + col0 + 4);
    }
#pragma unroll
    for (int i = 0; i < 8; ++i) {
        const long long off = (long long)(row0 + i) * ldc + col0;
        float4 c0 = make_float4(acc[i][0], acc[i][1], acc[i][2], acc[i][3]);
        float4 c1 = make_float4(acc[i][4], acc[i][5], acc[i][6], acc[i][7]);
        if (BIAS) {
            c0.x += bi0.x; c0.y += bi0.y; c0.z += bi0.z; c0.w += bi0.w;
            c1.x += bi1.x; c1.y += bi1.y; c1.z += bi1.z; c1.w += bi1.w;
        }
        *reinterpret_cast<float4*>(C + off) = c0;
        *reinterpret_cast<float4*>(C + off + 4) = c1;
        if (AVEPI) {
            float4 t0 = *reinterpret_cast<const float4*>(text + off);
            float4 t1 = *reinterpret_cast<const float4*>(text + off + 4);
            float4 f0 = make_float4(c0.x + t0.x, c0.y + t0.y, c0.z + t0.z, c0.w + t0.w);
            float4 f1 = make_float4(c1.x + t1.x, c1.y + t1.y, c1.z + t1.z, c1.w + t1.w);
            *reinterpret_cast<float4*>(feat + off) = f0;
            *reinterpret_cast<float4*>(feat + off + 4) = f1;
        }
    }
}

// ---------------------------------------------------------------------------
// Row softmax over 2048 columns, in place, fused * (1/sqrt(1024)).
// One CTA (256 threads) per row; 8 elements/thread kept in registers.
// ---------------------------------------------------------------------------
__global__ void __launch_bounds__(256) softmax_k(float* __restrict__ Sm)
{
    __shared__ float red[32];
    const long long row = blockIdx.x;
    float* p = Sm + row * 2048;
    const int t = threadIdx.x;
    const int lane = t & 31, w = t >> 5;

    float4 v0 = reinterpret_cast<const float4*>(p)[t];
    float4 v1 = reinterpret_cast<const float4*>(p)[t + 256];

    float m = fmaxf(fmaxf(fmaxf(v0.x, v0.y), fmaxf(v0.z, v0.w)),
                    fmaxf(fmaxf(v1.x, v1.y), fmaxf(v1.z, v1.w)));
#pragma unroll
    for (int o = 16; o > 0; o >>= 1) m = fmaxf(m, __shfl_xor_sync(0xFFFFFFFFu, m, o));
    if (lane == 0) red[w] = m;
    __syncthreads();
    if (t < 32) {
        float x = (t < 8) ? red[t] : -3.4e38f;
#pragma unroll
        for (int o = 4; o > 0; o >>= 1) x = fmaxf(x, __shfl_xor_sync(0xFFFFFFFFu, x, o));
        if (t == 0) red[0] = x;
    }
    __syncthreads();
    m = red[0];
    __syncthreads();   // protect red[] reuse

    float e[8];
    e[0] = expf(v0.x - m); e[1] = expf(v0.y - m); e[2] = expf(v0.z - m); e[3] = expf(v0.w - m);
    e[4] = expf(v1.x - m); e[5] = expf(v1.y - m); e[6] = expf(v1.z - m); e[7] = expf(v1.w - m);
    float s = ((e[0] + e[1]) + (e[2] + e[3])) + ((e[4] + e[5]) + (e[6] + e[7]));
#pragma unroll
    for (int o = 16; o > 0; o >>= 1) s += __shfl_xor_sync(0xFFFFFFFFu, s, o);
    if (lane == 0) red[w] = s;
    __syncthreads();
    if (t < 32) {
        float x = (t < 8) ? red[t] : 0.0f;
#pragma unroll
        for (int o = 4; o > 0; o >>= 1) x += __shfl_xor_sync(0xFFFFFFFFu, x, o);
        if (t == 0) red[0] = x;
    }
    __syncthreads();
    s = red[0];

    const float inv = 0.03125f / s;   // (1/sqrt(1024)) / sum
    float4 o0 = make_float4(e[0] * inv, e[1] * inv, e[2] * inv, e[3] * inv);
    float4 o1 = make_float4(e[4] * inv, e[5] * inv, e[6] * inv, e[7] * inv);
    reinterpret_cast<float4*>(p)[t] = o0;
    reinterpret_cast<float4*>(p)[t + 256] = o1;
}

// ---------------------------------------------------------------------------
extern "C" void kernel_launch(void* const* d_in, const int* in_sizes, int n_in,
                              void* d_out, int out_size)
{
    const float* img  = (const float*)d_in[0];
    const float* text = (const float*)d_in[1];
    const float* q_w  = (const float*)d_in[2];
    const float* q_b  = (const float*)d_in[3];
    const float* k_w  = (const float*)d_in[4];
    const float* k_b  = (const float*)d_in[5];
    const float* v_w  = (const float*)d_in[6];
    const float* v_b  = (const float*)d_in[7];
    float* out = (float*)d_out;

    float *gq, *gk, *gv, *gs;
    cudaGetSymbolAddress((void**)&gq, g_Q);
    cudaGetSymbolAddress((void**)&gk, g_K);
    cudaGetSymbolAddress((void**)&gv, g_V);
    cudaGetSymbolAddress((void**)&gs, g_S);

    const dim3 blk(256);

    // --- Phase A: Q/K/V projections, [16384,1024] = X @ W^T + b ---
    const dim3 gA(1024 / BN, 16384 / BM, 1);
    gemm_k<true, true, false><<<gA, blk>>>(img,  q_w, q_b, gq, nullptr, nullptr,
                                           1024, 1024, 1024, 1024, 0, 0, 0);
    gemm_k<true, true, false><<<gA, blk>>>(text, k_w, k_b, gk, nullptr, nullptr,
                                           1024, 1024, 1024, 1024, 0, 0, 0);
    gemm_k<true, true, false><<<gA, blk>>>(text, v_w, v_b, gv, nullptr, nullptr,
                                           1024, 1024, 1024, 1024, 0, 0, 0);

    // --- Phase B: scores[b] = Q_b @ K_b^T, [2048,2048], K=1024, 8 batches ---
    const dim3 gB(2048 / BN, 2048 / BM, 8);
    gemm_k<true, false, false><<<gB, blk>>>(gq, gk, nullptr, gs, nullptr, nullptr,
                                            1024, 1024, 1024, 2048,
                                            2048LL * 1024, 2048LL * 1024, 2048LL * 2048);

    // --- Phase C: row softmax * 1/32, in place on scores ---
    softmax_k<<<8 * 2048, 256>>>(gs);

    // --- Phase D: output[b] = atten_b @ V_b ; feature = output + text ---
    const dim3 gD(1024 / BN, 2048 / BM, 8);
    gemm_k<false, false, true><<<gD, blk>>>(gs, gv, nullptr,
                                            out, text, out + 16777216LL,
                                            2048, 2048, 1024, 1024,
                                            2048LL * 2048, 2048LL * 1024, 2048LL * 1024);

    (void)in_sizes; (void)n_in; (void)out_size;
}

// round 9
// speedup vs baseline: 1.0001x; 1.0001x over previous
#include <cuda_runtime.h>
#include <math.h>

// ---------------------------------------------------------------------------
// AV_Attention: B=8, S=2048, INPUT_DIM=1024, DIM_K=DIM_V=1024, fp32.
//   Q = img @ q_w^T + q_b ; K = text @ k_w^T + k_b ; V = text @ v_w^T + v_b
//   scores = Q @ K^T (per batch)  [NO pre-softmax scaling — quirk!]
//   atten  = softmax(scores) * (1/sqrt(1024))
//   output = atten @ V ; feature = output + text
// Outputs flattened: d_out[0:16777216)=output, d_out[16777216:33554432)=feature
// ---------------------------------------------------------------------------

static __device__ float g_Q[16777216];   // 64 MB
static __device__ float g_K[16777216];   // 64 MB
static __device__ float g_V[16777216];   // 64 MB
static __device__ float g_S[33554432];   // 128 MB (scores / atten)

constexpr int BM = 128, BN = 128, BK = 16;

// ---------------------------------------------------------------------------
// Generic 128x128x16 double-buffered SGEMM.
//  C = A @ B^T (TRANSB=true, B is [N,K] row-major)   or
//  C = A @ B   (TRANSB=false, B is [K,N] row-major)
//  BIAS : add bias[col]
//  AVEPI: write C and feat = C + text
// Grid: (N/128, M/128, batches). All dims must divide the tiles (they do).
// ---------------------------------------------------------------------------
template <bool TRANSB, bool BIAS, bool AVEPI>
__global__ void __launch_bounds__(256, 2)
gemm_k(const float* __restrict__ A, const float* __restrict__ B,
       const float* __restrict__ bias, float* __restrict__ C,
       const float* __restrict__ text, float* __restrict__ feat,
       int K, int lda, int ldb, int ldc,
       long long sA, long long sB, long long sC)
{
    __shared__ float As[2][BK][BM + 4];
    __shared__ float Bs[2][BK][BN + 4];

    const int z = blockIdx.z;
    A += (long long)z * sA;
    B += (long long)z * sB;
    C += (long long)z * sC;
    if (AVEPI) { text += (long long)z * sC; feat += (long long)z * sC; }

    const int tid = threadIdx.x;
    const int tx = tid & 15;
    const int ty = tid >> 4;
    const int bx = blockIdx.x, by = blockIdx.y;

    // A loader: 128 rows x 16 k, transpose-store. 2 float4 per thread.
    const int arow = tid >> 2;            // 0..63
    const int acol = (tid & 3) << 2;      // 0,4,8,12
    const float* Aptr0 = A + (long long)(by * BM + arow) * lda + acol;
    const float* Aptr1 = Aptr0 + 64LL * lda;

    // B loader
    const float* Bptr0;
    const float* Bptr1;
    int bk_row = 0, bn_col = 0;
    if (TRANSB) {
        Bptr0 = B + (long long)(bx * BN + arow) * ldb + acol;
        Bptr1 = Bptr0 + 64LL * ldb;
    } else {
        bk_row = tid >> 5;                // 0..7
        bn_col = (tid & 31) << 2;         // 0..124
        Bptr0 = B + (long long)bk_row * ldb + bx * BN + bn_col;
        Bptr1 = Bptr0 + 8LL * ldb;
    }

    auto ld_tile = [&](int k0, float4& va0, float4& va1, float4& vb0, float4& vb1) {
        va0 = *reinterpret_cast<const float4*>(Aptr0 + k0);
        va1 = *reinterpret_cast<const float4*>(Aptr1 + k0);
        if (TRANSB) {
            vb0 = *reinterpret_cast<const float4*>(Bptr0 + k0);
            vb1 = *reinterpret_cast<const float4*>(Bptr1 + k0);
        } else {
            vb0 = *reinterpret_cast<const float4*>(Bptr0 + (long long)k0 * ldb);
            vb1 = *reinterpret_cast<const float4*>(Bptr1 + (long long)k0 * ldb);
        }
    };

    auto st_tile = [&](int s, float4 va0, float4 va1, float4 vb0, float4 vb1) {
        As[s][acol + 0][arow] = va0.x;
        As[s][acol + 1][arow] = va0.y;
        As[s][acol + 2][arow] = va0.z;
        As[s][acol + 3][arow] = va0.w;
        As[s][acol + 0][arow + 64] = va1.x;
        As[s][acol + 1][arow + 64] = va1.y;
        As[s][acol + 2][arow + 64] = va1.z;
        As[s][acol + 3][arow + 64] = va1.w;
        if (TRANSB) {
            Bs[s][acol + 0][arow] = vb0.x;
            Bs[s][acol + 1][arow] = vb0.y;
            Bs[s][acol + 2][arow] = vb0.z;
            Bs[s][acol + 3][arow] = vb0.w;
            Bs[s][acol + 0][arow + 64] = vb1.x;
            Bs[s][acol + 1][arow + 64] = vb1.y;
            Bs[s][acol + 2][arow + 64] = vb1.z;
            Bs[s][acol + 3][arow + 64] = vb1.w;
        } else {
            *reinterpret_cast<float4*>(&Bs[s][bk_row][bn_col]) = vb0;
            *reinterpret_cast<float4*>(&Bs[s][bk_row + 8][bn_col]) = vb1;
        }
    };

    float acc[8][8];
#pragma unroll
    for (int i = 0; i < 8; ++i)
#pragma unroll
        for (int j = 0; j < 8; ++j) acc[i][j] = 0.0f;

    {
        float4 a0, a1, b0, b1;
        ld_tile(0, a0, a1, b0, b1);
        st_tile(0, a0, a1, b0, b1);
    }
    __syncthreads();

    const int nk = K / BK;
    for (int kt = 0; kt < nk; ++kt) {
        const int s = kt & 1;
        float4 na0, na1, nb0, nb1;
        const bool pf = (kt + 1 < nk);
        if (pf) ld_tile((kt + 1) * BK, na0, na1, nb0, nb1);

#pragma unroll
        for (int kk = 0; kk < BK; ++kk) {
            float4 xa0 = *reinterpret_cast<const float4*>(&As[s][kk][ty * 8]);
            float4 xa1 = *reinterpret_cast<const float4*>(&As[s][kk][ty * 8 + 4]);
            float4 xb0 = *reinterpret_cast<const float4*>(&Bs[s][kk][tx * 8]);
            float4 xb1 = *reinterpret_cast<const float4*>(&Bs[s][kk][tx * 8 + 4]);
            float ar[8] = {xa0.x, xa0.y, xa0.z, xa0.w, xa1.x, xa1.y, xa1.z, xa1.w};
            float br[8] = {xb0.x, xb0.y, xb0.z, xb0.w, xb1.x, xb1.y, xb1.z, xb1.w};
#pragma unroll
            for (int i = 0; i < 8; ++i)
#pragma unroll
                for (int j = 0; j < 8; ++j)
                    acc[i][j] = fmaf(ar[i], br[j], acc[i][j]);
        }

        if (pf) st_tile(s ^ 1, na0, na1, nb0, nb1);
        __syncthreads();
    }

    // Epilogue
    const int row0 = by * BM + ty * 8;
    const int col0 = bx * BN + tx * 8;
    float4 bi0, bi1;
    if (BIAS) {
        bi0 = *reinterpret_cast<const float4*>(bias + col0);
        bi1 = *reinterpret_cast<const float4*>(bias + col0 + 4);
    }
#pragma unroll
    for (int i = 0; i < 8; ++i) {
        const long long off = (long long)(row0 + i) * ldc + col0;
        float4 c0 = make_float4(acc[i][0], acc[i][1], acc[i][2], acc[i][3]);
        float4 c1 = make_float4(acc[i][4], acc[i][5], acc[i][6], acc[i][7]);
        if (BIAS) {
            c0.x += bi0.x; c0.y += bi0.y; c0.z += bi0.z; c0.w += bi0.w;
            c1.x += bi1.x; c1.y += bi1.y; c1.z += bi1.z; c1.w += bi1.w;
        }
        *reinterpret_cast<float4*>(C + off) = c0;
        *reinterpret_cast<float4*>(C + off + 4) = c1;
        if (AVEPI) {
            float4 t0 = *reinterpret_cast<const float4*>(text + off);
            float4 t1 = *reinterpret_cast<const float4*>(text + off + 4);
            float4 f0 = make_float4(c0.x + t0.x, c0.y + t0.y, c0.z + t0.z, c0.w + t0.w);
            float4 f1 = make_float4(c1.x + t1.x, c1.y + t1.y, c1.z + t1.z, c1.w + t1.w);
            *reinterpret_cast<float4*>(feat + off) = f0;
            *reinterpret_cast<float4*>(feat + off + 4) = f1;
        }
    }
}

// ---------------------------------------------------------------------------
// Row softmax over 2048 columns, in place, fused * (1/sqrt(1024)).
// One CTA (256 threads) per row; 8 elements/thread kept in registers.
// ---------------------------------------------------------------------------
__global__ void __launch_bounds__(256) softmax_k(float* __restrict__ Sm)
{
    __shared__ float red[32];
    const long long row = blockIdx.x;
    float* p = Sm + row * 2048;
    const int t = threadIdx.x;
    const int lane = t & 31, w = t >> 5;

    float4 v0 = reinterpret_cast<const float4*>(p)[t];
    float4 v1 = reinterpret_cast<const float4*>(p)[t + 256];

    float m = fmaxf(fmaxf(fmaxf(v0.x, v0.y), fmaxf(v0.z, v0.w)),
                    fmaxf(fmaxf(v1.x, v1.y), fmaxf(v1.z, v1.w)));
#pragma unroll
    for (int o = 16; o > 0; o >>= 1) m = fmaxf(m, __shfl_xor_sync(0xFFFFFFFFu, m, o));
    if (lane == 0) red[w] = m;
    __syncthreads();
    if (t < 32) {
        float x = (t < 8) ? red[t] : -3.4e38f;
#pragma unroll
        for (int o = 4; o > 0; o >>= 1) x = fmaxf(x, __shfl_xor_sync(0xFFFFFFFFu, x, o));
        if (t == 0) red[0] = x;
    }
    __syncthreads();
    m = red[0];
    __syncthreads();   // protect red[] reuse

    float e[8];
    e[0] = expf(v0.x - m); e[1] = expf(v0.y - m); e[2] = expf(v0.z - m); e[3] = expf(v0.w - m);
    e[4] = expf(v1.x - m); e[5] = expf(v1.y - m); e[6] = expf(v1.z - m); e[7] = expf(v1.w - m);
    float s = ((e[0] + e[1]) + (e[2] + e[3])) + ((e[4] + e[5]) + (e[6] + e[7]));
#pragma unroll
    for (int o = 16; o > 0; o >>= 1) s += __shfl_xor_sync(0xFFFFFFFFu, s, o);
    if (lane == 0) red[w] = s;
    __syncthreads();
    if (t < 32) {
        float x = (t < 8) ? red[t] : 0.0f;
#pragma unroll
        for (int o = 4; o > 0; o >>= 1) x += __shfl_xor_sync(0xFFFFFFFFu, x, o);
        if (t == 0) red[0] = x;
    }
    __syncthreads();
    s = red[0];

    const float inv = 0.03125f / s;   // (1/sqrt(1024)) / sum
    float4 o0 = make_float4(e[0] * inv, e[1] * inv, e[2] * inv, e[3] * inv);
    float4 o1 = make_float4(e[4] * inv, e[5] * inv, e[6] * inv, e[7] * inv);
    reinterpret_cast<float4*>(p)[t] = o0;
    reinterpret_cast<float4*>(p)[t + 256] = o1;
}

// ---------------------------------------------------------------------------
extern "C" void kernel_launch(void* const* d_in, const int* in_sizes, int n_in,
                              void* d_out, int out_size)
{
    const float* img  = (const float*)d_in[0];
    const float* text = (const float*)d_in[1];
    const float* q_w  = (const float*)d_in[2];
    const float* q_b  = (const float*)d_in[3];
    const float* k_w  = (const float*)d_in[4];
    const float* k_b  = (const float*)d_in[5];
    const float* v_w  = (const float*)d_in[6];
    const float* v_b  = (const float*)d_in[7];
    float* out = (float*)d_out;

    float *gq, *gk, *gv, *gs;
    cudaGetSymbolAddress((void**)&gq, g_Q);
    cudaGetSymbolAddress((void**)&gk, g_K);
    cudaGetSymbolAddress((void**)&gv, g_V);
    cudaGetSymbolAddress((void**)&gs, g_S);

    const dim3 blk(256);

    // --- Phase A: Q/K/V projections, [16384,1024] = X @ W^T + b ---
    const dim3 gA(1024 / BN, 16384 / BM, 1);
    gemm_k<true, true, false><<<gA, blk>>>(img,  q_w, q_b, gq, nullptr, nullptr,
                                           1024, 1024, 1024, 1024, 0, 0, 0);
    gemm_k<true, true, false><<<gA, blk>>>(text, k_w, k_b, gk, nullptr, nullptr,
                                           1024, 1024, 1024, 1024, 0, 0, 0);
    gemm_k<true, true, false><<<gA, blk>>>(text, v_w, v_b, gv, nullptr, nullptr,
                                           1024, 1024, 1024, 1024, 0, 0, 0);

    // --- Phase B: scores[b] = Q_b @ K_b^T, [2048,2048], K=1024, 8 batches ---
    const dim3 gB(2048 / BN, 2048 / BM, 8);
    gemm_k<true, false, false><<<gB, blk>>>(gq, gk, nullptr, gs, nullptr, nullptr,
                                            1024, 1024, 1024, 2048,
                                            2048LL * 1024, 2048LL * 1024, 2048LL * 2048);

    // --- Phase C: row softmax * 1/32, in place on scores ---
    softmax_k<<<8 * 2048, 256>>>(gs);

    // --- Phase D: output[b] = atten_b @ V_b ; feature = output + text ---
    const dim3 gD(1024 / BN, 2048 / BM, 8);
    gemm_k<false, false, true><<<gD, blk>>>(gs, gv, nullptr,
                                            out, text, out + 16777216LL,
                                            2048, 2048, 1024, 1024,
                                            2048LL * 2048, 2048LL * 1024, 2048LL * 1024);

    (void)in_sizes; (void)n_in; (void)out_size;
}

// round 10
// speedup vs baseline: 1.0012x; 1.0012x over previous
#include <cuda_runtime.h>
#include <math.h>

// ---------------------------------------------------------------------------
// AV_Attention: B=8, S=2048, INPUT_DIM=1024, DIM_K=DIM_V=1024, fp32.
//   Q = img @ q_w^T + q_b ; K = text @ k_w^T + k_b ; V = text @ v_w^T + v_b
//   scores = Q @ K^T (per batch)  [NO pre-softmax scaling — quirk!]
//   atten  = softmax(scores) * (1/sqrt(1024))
//   output = atten @ V ; feature = output + text
// Outputs flattened: d_out[0:16777216)=output, d_out[16777216:33554432)=feature
// ---------------------------------------------------------------------------

static __device__ float g_Q[16777216];   // 64 MB
static __device__ float g_K[16777216];   // 64 MB
static __device__ float g_V[16777216];   // 64 MB
static __device__ float g_S[33554432];   // 128 MB (scores / atten)

constexpr int BM = 128, BN = 128, BK = 16;

// ---------------------------------------------------------------------------
// Generic 128x128x16 double-buffered SGEMM.
//  C = A @ B^T (TRANSB=true, B is [N,K] row-major)   or
//  C = A @ B   (TRANSB=false, B is [K,N] row-major)
//  BIAS : add bias[col]
//  AVEPI: write C and feat = C + text
// Grid: (N/128, M/128, batches). All dims must divide the tiles (they do).
// ---------------------------------------------------------------------------
template <bool TRANSB, bool BIAS, bool AVEPI>
__global__ void __launch_bounds__(256, 2)
gemm_k(const float* __restrict__ A, const float* __restrict__ B,
       const float* __restrict__ bias, float* __restrict__ C,
       const float* __restrict__ text, float* __restrict__ feat,
       int K, int lda, int ldb, int ldc,
       long long sA, long long sB, long long sC)
{
    __shared__ float As[2][BK][BM + 4];
    __shared__ float Bs[2][BK][BN + 4];

    const int z = blockIdx.z;
    A += (long long)z * sA;
    B += (long long)z * sB;
    C += (long long)z * sC;
    if (AVEPI) { text += (long long)z * sC; feat += (long long)z * sC; }

    const int tid = threadIdx.x;
    const int tx = tid & 15;
    const int ty = tid >> 4;
    const int bx = blockIdx.x, by = blockIdx.y;

    // A loader: 128 rows x 16 k, transpose-store. 2 float4 per thread.
    const int arow = tid >> 2;            // 0..63
    const int acol = (tid & 3) << 2;      // 0,4,8,12
    const float* Aptr0 = A + (long long)(by * BM + arow) * lda + acol;
    const float* Aptr1 = Aptr0 + 64LL * lda;

    // B loader
    const float* Bptr0;
    const float* Bptr1;
    int bk_row = 0, bn_col = 0;
    if (TRANSB) {
        Bptr0 = B + (long long)(bx * BN + arow) * ldb + acol;
        Bptr1 = Bptr0 + 64LL * ldb;
    } else {
        bk_row = tid >> 5;                // 0..7
        bn_col = (tid & 31) << 2;         // 0..124
        Bptr0 = B + (long long)bk_row * ldb + bx * BN + bn_col;
        Bptr1 = Bptr0 + 8LL * ldb;
    }

    auto ld_tile = [&](int k0, float4& va0, float4& va1, float4& vb0, float4& vb1) {
        va0 = *reinterpret_cast<const float4*>(Aptr0 + k0);
        va1 = *reinterpret_cast<const float4*>(Aptr1 + k0);
        if (TRANSB) {
            vb0 = *reinterpret_cast<const float4*>(Bptr0 + k0);
            vb1 = *reinterpret_cast<const float4*>(Bptr1 + k0);
        } else {
            vb0 = *reinterpret_cast<const float4*>(Bptr0 + (long long)k0 * ldb);
            vb1 = *reinterpret_cast<const float4*>(Bptr1 + (long long)k0 * ldb);
        }
    };

    auto st_tile = [&](int s, float4 va0, float4 va1, float4 vb0, float4 vb1) {
        As[s][acol + 0][arow] = va0.x;
        As[s][acol + 1][arow] = va0.y;
        As[s][acol + 2][arow] = va0.z;
        As[s][acol + 3][arow] = va0.w;
        As[s][acol + 0][arow + 64] = va1.x;
        As[s][acol + 1][arow + 64] = va1.y;
        As[s][acol + 2][arow + 64] = va1.z;
        As[s][acol + 3][arow + 64] = va1.w;
        if (TRANSB) {
            Bs[s][acol + 0][arow] = vb0.x;
            Bs[s][acol + 1][arow] = vb0.y;
            Bs[s][acol + 2][arow] = vb0.z;
            Bs[s][acol + 3][arow] = vb0.w;
            Bs[s][acol + 0][arow + 64] = vb1.x;
            Bs[s][acol + 1][arow + 64] = vb1.y;
            Bs[s][acol + 2][arow + 64] = vb1.z;
            Bs[s][acol + 3][arow + 64] = vb1.w;
        } else {
            *reinterpret_cast<float4*>(&Bs[s][bk_row][bn_col]) = vb0;
            *reinterpret_cast<float4*>(&Bs[s][bk_row + 8][bn_col]) = vb1;
        }
    };

    float acc[8][8];
#pragma unroll
    for (int i = 0; i < 8; ++i)
#pragma unroll
        for (int j = 0; j < 8; ++j) acc[i][j] = 0.0f;

    {
        float4 a0, a1, b0, b1;
        ld_tile(0, a0, a1, b0, b1);
        st_tile(0, a0, a1, b0, b1);
    }
    __syncthreads();

    const int nk = K / BK;
    for (int kt = 0; kt < nk; ++kt) {
        const int s = kt & 1;
        float4 na0, na1, nb0, nb1;
        const bool pf = (kt + 1 < nk);
        if (pf) ld_tile((kt + 1) * BK, na0, na1, nb0, nb1);

#pragma unroll
        for (int kk = 0; kk < BK; ++kk) {
            float4 xa0 = *reinterpret_cast<const float4*>(&As[s][kk][ty * 8]);
            float4 xa1 = *reinterpret_cast<const float4*>(&As[s][kk][ty * 8 + 4]);
            float4 xb0 = *reinterpret_cast<const float4*>(&Bs[s][kk][tx * 8]);
            float4 xb1 = *reinterpret_cast<const float4*>(&Bs[s][kk][tx * 8 + 4]);
            float ar[8] = {xa0.x, xa0.y, xa0.z, xa0.w, xa1.x, xa1.y, xa1.z, xa1.w};
            float br[8] = {xb0.x, xb0.y, xb0.z, xb0.w, xb1.x, xb1.y, xb1.z, xb1.w};
#pragma unroll
            for (int i = 0; i < 8; ++i)
#pragma unroll
                for (int j = 0; j < 8; ++j)
                    acc[i][j] = fmaf(ar[i], br[j], acc[i][j]);
        }

        if (pf) st_tile(s ^ 1, na0, na1, nb0, nb1);
        __syncthreads();
    }

    // Epilogue
    const int row0 = by * BM + ty * 8;
    const int col0 = bx * BN + tx * 8;
    float4 bi0, bi1;
    if (BIAS) {
        bi0 = *reinterpret_cast<const float4*>(bias + col0);
        bi1 = *reinterpret_cast<const float4*>(bias + col0 + 4);
    }
#pragma unroll
    for (int i = 0; i < 8; ++i) {
        const long long off = (long long)(row0 + i) * ldc + col0;
        float4 c0 = make_float4(acc[i][0], acc[i][1], acc[i][2], acc[i][3]);
        float4 c1 = make_float4(acc[i][4], acc[i][5], acc[i][6], acc[i][7]);
        if (BIAS) {
            c0.x += bi0.x; c0.y += bi0.y; c0.z += bi0.z; c0.w += bi0.w;
            c1.x += bi1.x; c1.y += bi1.y; c1.z += bi1.z; c1.w += bi1.w;
        }
        *reinterpret_cast<float4*>(C + off) = c0;
        *reinterpret_cast<float4*>(C + off + 4) = c1;
        if (AVEPI) {
            float4 t0 = *reinterpret_cast<const float4*>(text + off);
            float4 t1 = *reinterpret_cast<const float4*>(text + off + 4);
            float4 f0 = make_float4(c0.x + t0.x, c0.y + t0.y, c0.z + t0.z, c0.w + t0.w);
            float4 f1 = make_float4(c1.x + t1.x, c1.y + t1.y, c1.z + t1.z, c1.w + t1.w);
            *reinterpret_cast<float4*>(feat + off) = f0;
            *reinterpret_cast<float4*>(feat + off + 4) = f1;
        }
    }
}

// ---------------------------------------------------------------------------
// Row softmax over 2048 columns, in place, fused * (1/sqrt(1024)).
// One CTA (256 threads) per row; 8 elements/thread kept in registers.
// ---------------------------------------------------------------------------
__global__ void __launch_bounds__(256) softmax_k(float* __restrict__ Sm)
{
    __shared__ float red[32];
    const long long row = blockIdx.x;
    float* p = Sm + row * 2048;
    const int t = threadIdx.x;
    const int lane = t & 31, w = t >> 5;

    float4 v0 = reinterpret_cast<const float4*>(p)[t];
    float4 v1 = reinterpret_cast<const float4*>(p)[t + 256];

    float m = fmaxf(fmaxf(fmaxf(v0.x, v0.y), fmaxf(v0.z, v0.w)),
                    fmaxf(fmaxf(v1.x, v1.y), fmaxf(v1.z, v1.w)));
#pragma unroll
    for (int o = 16; o > 0; o >>= 1) m = fmaxf(m, __shfl_xor_sync(0xFFFFFFFFu, m, o));
    if (lane == 0) red[w] = m;
    __syncthreads();
    if (t < 32) {
        float x = (t < 8) ? red[t] : -3.4e38f;
#pragma unroll
        for (int o = 4; o > 0; o >>= 1) x = fmaxf(x, __shfl_xor_sync(0xFFFFFFFFu, x, o));
        if (t == 0) red[0] = x;
    }
    __syncthreads();
    m = red[0];
    __syncthreads();   // protect red[] reuse

    float e[8];
    e[0] = expf(v0.x - m); e[1] = expf(v0.y - m); e[2] = expf(v0.z - m); e[3] = expf(v0.w - m);
    e[4] = expf(v1.x - m); e[5] = expf(v1.y - m); e[6] = expf(v1.z - m); e[7] = expf(v1.w - m);
    float s = ((e[0] + e[1]) + (e[2] + e[3])) + ((e[4] + e[5]) + (e[6] + e[7]));
#pragma unroll
    for (int o = 16; o > 0; o >>= 1) s += __shfl_xor_sync(0xFFFFFFFFu, s, o);
    if (lane == 0) red[w] = s;
    __syncthreads();
    if (t < 32) {
        float x = (t < 8) ? red[t] : 0.0f;
#pragma unroll
        for (int o = 4; o > 0; o >>= 1) x += __shfl_xor_sync(0xFFFFFFFFu, x, o);
        if (t == 0) red[0] = x;
    }
    __syncthreads();
    s = red[0];

    const float inv = 0.03125f / s;   // (1/sqrt(1024)) / sum
    float4 o0 = make_float4(e[0] * inv, e[1] * inv, e[2] * inv, e[3] * inv);
    float4 o1 = make_float4(e[4] * inv, e[5] * inv, e[6] * inv, e[7] * inv);
    reinterpret_cast<float4*>(p)[t] = o0;
    reinterpret_cast<float4*>(p)[t + 256] = o1;
}

// ---------------------------------------------------------------------------
extern "C" void kernel_launch(void* const* d_in, const int* in_sizes, int n_in,
                              void* d_out, int out_size)
{
    const float* img  = (const float*)d_in[0];
    const float* text = (const float*)d_in[1];
    const float* q_w  = (const float*)d_in[2];
    const float* q_b  = (const float*)d_in[3];
    const float* k_w  = (const float*)d_in[4];
    const float* k_b  = (const float*)d_in[5];
    const float* v_w  = (const float*)d_in[6];
    const float* v_b  = (const float*)d_in[7];
    float* out = (float*)d_out;

    float *gq, *gk, *gv, *gs;
    cudaGetSymbolAddress((void**)&gq, g_Q);
    cudaGetSymbolAddress((void**)&gk, g_K);
    cudaGetSymbolAddress((void**)&gv, g_V);
    cudaGetSymbolAddress((void**)&gs, g_S);

    const dim3 blk(256);

    // --- Phase A: Q/K/V projections, [16384,1024] = X @ W^T + b ---
    const dim3 gA(1024 / BN, 16384 / BM, 1);
    gemm_k<true, true, false><<<gA, blk>>>(img,  q_w, q_b, gq, nullptr, nullptr,
                                           1024, 1024, 1024, 1024, 0, 0, 0);
    gemm_k<true, true, false><<<gA, blk>>>(text, k_w, k_b, gk, nullptr, nullptr,
                                           1024, 1024, 1024, 1024, 0, 0, 0);
    gemm_k<true, true, false><<<gA, blk>>>(text, v_w, v_b, gv, nullptr, nullptr,
                                           1024, 1024, 1024, 1024, 0, 0, 0);

    // --- Phase B: scores[b] = Q_b @ K_b^T, [2048,2048], K=1024, 8 batches ---
    const dim3 gB(2048 / BN, 2048 / BM, 8);
    gemm_k<true, false, false><<<gB, blk>>>(gq, gk, nullptr, gs, nullptr, nullptr,
                                            1024, 1024, 1024, 2048,
                                            2048LL * 1024, 2048LL * 1024, 2048LL * 2048);

    // --- Phase C: row softmax * 1/32, in place on scores ---
    softmax_k<<<8 * 2048, 256>>>(gs);

    // --- Phase D: output[b] = atten_b @ V_b ; feature = output + text ---
    const dim3 gD(1024 / BN, 2048 / BM, 8);
    gemm_k<false, false, true><<<gD, blk>>>(gs, gv, nullptr,
                                            out, text, out + 16777216LL,
                                            2048, 2048, 1024, 1024,
                                            2048LL * 2048, 2048LL * 1024, 2048LL * 1024);

    (void)in_sizes; (void)n_in; (void)out_size;
}

// round 11
// speedup vs baseline: 1.0013x; 1.0001x over previous
#include <cuda_runtime.h>
#include <math.h>

// ---------------------------------------------------------------------------
// AV_Attention: B=8, S=2048, INPUT_DIM=1024, DIM_K=DIM_V=1024, fp32.
//   Q = img @ q_w^T + q_b ; K = text @ k_w^T + k_b ; V = text @ v_w^T + v_b
//   scores = Q @ K^T (per batch)  [NO pre-softmax scaling — quirk!]
//   atten  = softmax(scores) * (1/sqrt(1024))
//   output = atten @ V ; feature = output + text
// Outputs flattened: d_out[0:16777216)=output, d_out[16777216:33554432)=feature
// ---------------------------------------------------------------------------

static __device__ float g_Q[16777216];   // 64 MB
static __device__ float g_K[16777216];   // 64 MB
static __device__ float g_V[16777216];   // 64 MB
static __device__ float g_S[33554432];   // 128 MB (scores / atten)

constexpr int BM = 128, BN = 128, BK = 16;

// ---------------------------------------------------------------------------
// Generic 128x128x16 double-buffered SGEMM.
//  C = A @ B^T (TRANSB=true, B is [N,K] row-major)   or
//  C = A @ B   (TRANSB=false, B is [K,N] row-major)
//  BIAS : add bias[col]
//  AVEPI: write C and feat = C + text
// Grid: (N/128, M/128, batches). All dims must divide the tiles (they do).
// ---------------------------------------------------------------------------
template <bool TRANSB, bool BIAS, bool AVEPI>
__global__ void __launch_bounds__(256, 2)
gemm_k(const float* __restrict__ A, const float* __restrict__ B,
       const float* __restrict__ bias, float* __restrict__ C,
       const float* __restrict__ text, float* __restrict__ feat,
       int K, int lda, int ldb, int ldc,
       long long sA, long long sB, long long sC)
{
    __shared__ float As[2][BK][BM + 4];
    __shared__ float Bs[2][BK][BN + 4];

    const int z = blockIdx.z;
    A += (long long)z * sA;
    B += (long long)z * sB;
    C += (long long)z * sC;
    if (AVEPI) { text += (long long)z * sC; feat += (long long)z * sC; }

    const int tid = threadIdx.x;
    const int tx = tid & 15;
    const int ty = tid >> 4;
    const int bx = blockIdx.x, by = blockIdx.y;

    // A loader: 128 rows x 16 k, transpose-store. 2 float4 per thread.
    const int arow = tid >> 2;            // 0..63
    const int acol = (tid & 3) << 2;      // 0,4,8,12
    const float* Aptr0 = A + (long long)(by * BM + arow) * lda + acol;
    const float* Aptr1 = Aptr0 + 64LL * lda;

    // B loader
    const float* Bptr0;
    const float* Bptr1;
    int bk_row = 0, bn_col = 0;
    if (TRANSB) {
        Bptr0 = B + (long long)(bx * BN + arow) * ldb + acol;
        Bptr1 = Bptr0 + 64LL * ldb;
    } else {
        bk_row = tid >> 5;                // 0..7
        bn_col = (tid & 31) << 2;         // 0..124
        Bptr0 = B + (long long)bk_row * ldb + bx * BN + bn_col;
        Bptr1 = Bptr0 + 8LL * ldb;
    }

    auto ld_tile = [&](int k0, float4& va0, float4& va1, float4& vb0, float4& vb1) {
        va0 = *reinterpret_cast<const float4*>(Aptr0 + k0);
        va1 = *reinterpret_cast<const float4*>(Aptr1 + k0);
        if (TRANSB) {
            vb0 = *reinterpret_cast<const float4*>(Bptr0 + k0);
            vb1 = *reinterpret_cast<const float4*>(Bptr1 + k0);
        } else {
            vb0 = *reinterpret_cast<const float4*>(Bptr0 + (long long)k0 * ldb);
            vb1 = *reinterpret_cast<const float4*>(Bptr1 + (long long)k0 * ldb);
        }
    };

    auto st_tile = [&](int s, float4 va0, float4 va1, float4 vb0, float4 vb1) {
        As[s][acol + 0][arow] = va0.x;
        As[s][acol + 1][arow] = va0.y;
        As[s][acol + 2][arow] = va0.z;
        As[s][acol + 3][arow] = va0.w;
        As[s][acol + 0][arow + 64] = va1.x;
        As[s][acol + 1][arow + 64] = va1.y;
        As[s][acol + 2][arow + 64] = va1.z;
        As[s][acol + 3][arow + 64] = va1.w;
        if (TRANSB) {
            Bs[s][acol + 0][arow] = vb0.x;
            Bs[s][acol + 1][arow] = vb0.y;
            Bs[s][acol + 2][arow] = vb0.z;
            Bs[s][acol + 3][arow] = vb0.w;
            Bs[s][acol + 0][arow + 64] = vb1.x;
            Bs[s][acol + 1][arow + 64] = vb1.y;
            Bs[s][acol + 2][arow + 64] = vb1.z;
            Bs[s][acol + 3][arow + 64] = vb1.w;
        } else {
            *reinterpret_cast<float4*>(&Bs[s][bk_row][bn_col]) = vb0;
            *reinterpret_cast<float4*>(&Bs[s][bk_row + 8][bn_col]) = vb1;
        }
    };

    float acc[8][8];
#pragma unroll
    for (int i = 0; i < 8; ++i)
#pragma unroll
        for (int j = 0; j < 8; ++j) acc[i][j] = 0.0f;

    {
        float4 a0, a1, b0, b1;
        ld_tile(0, a0, a1, b0, b1);
        st_tile(0, a0, a1, b0, b1);
    }
    __syncthreads();

    const int nk = K / BK;
    for (int kt = 0; kt < nk; ++kt) {
        const int s = kt & 1;
        float4 na0, na1, nb0, nb1;
        const bool pf = (kt + 1 < nk);
        if (pf) ld_tile((kt + 1) * BK, na0, na1, nb0, nb1);

#pragma unroll
        for (int kk = 0; kk < BK; ++kk) {
            float4 xa0 = *reinterpret_cast<const float4*>(&As[s][kk][ty * 8]);
            float4 xa1 = *reinterpret_cast<const float4*>(&As[s][kk][ty * 8 + 4]);
            float4 xb0 = *reinterpret_cast<const float4*>(&Bs[s][kk][tx * 8]);
            float4 xb1 = *reinterpret_cast<const float4*>(&Bs[s][kk][tx * 8 + 4]);
            float ar[8] = {xa0.x, xa0.y, xa0.z, xa0.w, xa1.x, xa1.y, xa1.z, xa1.w};
            float br[8] = {xb0.x, xb0.y, xb0.z, xb0.w, xb1.x, xb1.y, xb1.z, xb1.w};
#pragma unroll
            for (int i = 0; i < 8; ++i)
#pragma unroll
                for (int j = 0; j < 8; ++j)
                    acc[i][j] = fmaf(ar[i], br[j], acc[i][j]);
        }

        if (pf) st_tile(s ^ 1, na0, na1, nb0, nb1);
        __syncthreads();
    }

    // Epilogue
    const int row0 = by * BM + ty * 8;
    const int col0 = bx * BN + tx * 8;
    float4 bi0, bi1;
    if (BIAS) {
        bi0 = *reinterpret_cast<const float4*>(bias + col0);
        bi1 = *reinterpret_cast<const float4*>(bias + col0 + 4);
    }
#pragma unroll
    for (int i = 0; i < 8; ++i) {
        const long long off = (long long)(row0 + i) * ldc + col0;
        float4 c0 = make_float4(acc[i][0], acc[i][1], acc[i][2], acc[i][3]);
        float4 c1 = make_float4(acc[i][4], acc[i][5], acc[i][6], acc[i][7]);
        if (BIAS) {
            c0.x += bi0.x; c0.y += bi0.y; c0.z += bi0.z; c0.w += bi0.w;
            c1.x += bi1.x; c1.y += bi1.y; c1.z += bi1.z; c1.w += bi1.w;
        }
        *reinterpret_cast<float4*>(C + off) = c0;
        *reinterpret_cast<float4*>(C + off + 4) = c1;
        if (AVEPI) {
            float4 t0 = *reinterpret_cast<const float4*>(text + off);
            float4 t1 = *reinterpret_cast<const float4*>(text + off + 4);
            float4 f0 = make_float4(c0.x + t0.x, c0.y + t0.y, c0.z + t0.z, c0.w + t0.w);
            float4 f1 = make_float4(c1.x + t1.x, c1.y + t1.y, c1.z + t1.z, c1.w + t1.w);
            *reinterpret_cast<float4*>(feat + off) = f0;
            *reinterpret_cast<float4*>(feat + off + 4) = f1;
        }
    }
}

// ---------------------------------------------------------------------------
// Row softmax over 2048 columns, in place, fused * (1/sqrt(1024)).
// One CTA (256 threads) per row; 8 elements/thread kept in registers.
// ---------------------------------------------------------------------------
__global__ void __launch_bounds__(256) softmax_k(float* __restrict__ Sm)
{
    __shared__ float red[32];
    const long long row = blockIdx.x;
    float* p = Sm + row * 2048;
    const int t = threadIdx.x;
    const int lane = t & 31, w = t >> 5;

    float4 v0 = reinterpret_cast<const float4*>(p)[t];
    float4 v1 = reinterpret_cast<const float4*>(p)[t + 256];

    float m = fmaxf(fmaxf(fmaxf(v0.x, v0.y), fmaxf(v0.z, v0.w)),
                    fmaxf(fmaxf(v1.x, v1.y), fmaxf(v1.z, v1.w)));
#pragma unroll
    for (int o = 16; o > 0; o >>= 1) m = fmaxf(m, __shfl_xor_sync(0xFFFFFFFFu, m, o));
    if (lane == 0) red[w] = m;
    __syncthreads();
    if (t < 32) {
        float x = (t < 8) ? red[t] : -3.4e38f;
#pragma unroll
        for (int o = 4; o > 0; o >>= 1) x = fmaxf(x, __shfl_xor_sync(0xFFFFFFFFu, x, o));
        if (t == 0) red[0] = x;
    }
    __syncthreads();
    m = red[0];
    __syncthreads();   // protect red[] reuse

    float e[8];
    e[0] = expf(v0.x - m); e[1] = expf(v0.y - m); e[2] = expf(v0.z - m); e[3] = expf(v0.w - m);
    e[4] = expf(v1.x - m); e[5] = expf(v1.y - m); e[6] = expf(v1.z - m); e[7] = expf(v1.w - m);
    float s = ((e[0] + e[1]) + (e[2] + e[3])) + ((e[4] + e[5]) + (e[6] + e[7]));
#pragma unroll
    for (int o = 16; o > 0; o >>= 1) s += __shfl_xor_sync(0xFFFFFFFFu, s, o);
    if (lane == 0) red[w] = s;
    __syncthreads();
    if (t < 32) {
        float x = (t < 8) ? red[t] : 0.0f;
#pragma unroll
        for (int o = 4; o > 0; o >>= 1) x += __shfl_xor_sync(0xFFFFFFFFu, x, o);
        if (t == 0) red[0] = x;
    }
    __syncthreads();
    s = red[0];

    const float inv = 0.03125f / s;   // (1/sqrt(1024)) / sum
    float4 o0 = make_float4(e[0] * inv, e[1] * inv, e[2] * inv, e[3] * inv);
    float4 o1 = make_float4(e[4] * inv, e[5] * inv, e[6] * inv, e[7] * inv);
    reinterpret_cast<float4*>(p)[t] = o0;
    reinterpret_cast<float4*>(p)[t + 256] = o1;
}

// ---------------------------------------------------------------------------
extern "C" void kernel_launch(void* const* d_in, const int* in_sizes, int n_in,
                              void* d_out, int out_size)
{
    const float* img  = (const float*)d_in[0];
    const float* text = (const float*)d_in[1];
    const float* q_w  = (const float*)d_in[2];
    const float* q_b  = (const float*)d_in[3];
    const float* k_w  = (const float*)d_in[4];
    const float* k_b  = (const float*)d_in[5];
    const float* v_w  = (const float*)d_in[6];
    const float* v_b  = (const float*)d_in[7];
    float* out = (float*)d_out;

    float *gq, *gk, *gv, *gs;
    cudaGetSymbolAddress((void**)&gq, g_Q);
    cudaGetSymbolAddress((void**)&gk, g_K);
    cudaGetSymbolAddress((void**)&gv, g_V);
    cudaGetSymbolAddress((void**)&gs, g_S);

    const dim3 blk(256);

    // --- Phase A: Q/K/V projections, [16384,1024] = X @ W^T + b ---
    const dim3 gA(1024 / BN, 16384 / BM, 1);
    gemm_k<true, true, false><<<gA, blk>>>(img,  q_w, q_b, gq, nullptr, nullptr,
                                           1024, 1024, 1024, 1024, 0, 0, 0);
    gemm_k<true, true, false><<<gA, blk>>>(text, k_w, k_b, gk, nullptr, nullptr,
                                           1024, 1024, 1024, 1024, 0, 0, 0);
    gemm_k<true, true, false><<<gA, blk>>>(text, v_w, v_b, gv, nullptr, nullptr,
                                           1024, 1024, 1024, 1024, 0, 0, 0);

    // --- Phase B: scores[b] = Q_b @ K_b^T, [2048,2048], K=1024, 8 batches ---
    const dim3 gB(2048 / BN, 2048 / BM, 8);
    gemm_k<true, false, false><<<gB, blk>>>(gq, gk, nullptr, gs, nullptr, nullptr,
                                            1024, 1024, 1024, 2048,
                                            2048LL * 1024, 2048LL * 1024, 2048LL * 2048);

    // --- Phase C: row softmax * 1/32, in place on scores ---
    softmax_k<<<8 * 2048, 256>>>(gs);

    // --- Phase D: output[b] = atten_b @ V_b ; feature = output + text ---
    const dim3 gD(1024 / BN, 2048 / BM, 8);
    gemm_k<false, false, true><<<gD, blk>>>(gs, gv, nullptr,
                                            out, text, out + 16777216LL,
                                            2048, 2048, 1024, 1024,
                                            2048LL * 2048, 2048LL * 1024, 2048LL * 1024);

    (void)in_sizes; (void)n_in; (void)out_size;
}